// round 6
// baseline (speedup 1.0000x reference)
#include <cuda_runtime.h>

// ---------------- problem constants ----------------
constexpr int Bn = 64;      // batch
constexpr int Ln = 2048;    // sequence length
constexpr int Hn = 512;     // hidden
constexpr int JS = 16;      // j-slices (hidden split)
constexpr int BSL = 8;      // batch-slices
constexpr int NBLK = JS * BSL;   // 128 blocks, one per SM
constexpr int JB = Hn / JS;      // 32 hidden cols per block
constexpr int BB = Bn / BSL;     // 8 batches per block
constexpr int NTHR = 256;        // 8 warps

// Shared layout (floats):
//   Wsh[3][512][32]  : 49152   (gate-major, k-major, j contiguous -> conflict-free LDS)
//   union { hs[512][8] : 4096 ; scratch[8][768] : 6144 }
constexpr int WSH_FLOATS = 3 * Hn * JB;          // 49152
constexpr int UNION_FLOATS = 8 * 768;            // 6144 (>= 4096)
constexpr int SMEM_FLOATS = WSH_FLOATS + UNION_FLOATS;  // 55296
constexpr size_t SMEM_BYTES = (size_t)SMEM_FLOATS * 4;  // 221184 B <= 227KB

// Cross-step residual exchange, "transposed" layout [k*64 + b] so the
// staging reads coalesce and SMEM writes are conflict-free.
__device__ float g_res[2][Hn * Bn];
__device__ unsigned g_count;

__global__ void init_kernel() { g_count = 0u; }

__device__ __forceinline__ unsigned long long pack2(float v) {
    unsigned long long r;
    unsigned u = __float_as_uint(v);
    asm("mov.b64 %0, {%1, %1};" : "=l"(r) : "r"(u));
    return r;
}
__device__ __forceinline__ void fma2(unsigned long long& d,
                                     unsigned long long a,
                                     unsigned long long b) {
    asm("fma.rn.f32x2 %0, %1, %2, %0;" : "+l"(d) : "l"(a), "l"(b));
}

extern "C" __global__ void __launch_bounds__(NTHR, 1)
gru_persistent_kernel(const float* __restrict__ x,
                      const float* __restrict__ state,
                      const float* __restrict__ W_ih,
                      const float* __restrict__ W_hh,
                      const float* __restrict__ b_ih,
                      const float* __restrict__ b_hh,
                      const float* __restrict__ A,
                      float* __restrict__ out,
                      int write_final)
{
    extern __shared__ float smem[];
    float* Wsh = smem;                       // 49152 floats
    float* hs = smem + WSH_FLOATS;           // union region
    float* scratch = smem + WSH_FLOATS;      // union region

    const int tid = threadIdx.x;
    const int js = blockIdx.x % JS;
    const int bs = blockIdx.x / JS;
    const int lane = tid & 31;
    const int wrp = tid >> 5;

    // ---- one-time: weights slice into SMEM, layout Wsh[g][k][j] ----
    for (int r = 0; r < 3 * JB; r++) {
        int g = r >> 5, jl = r & 31;
        const float* src = W_hh + (size_t)(g * Hn + js * JB + jl) * Hn;
        for (int k = tid; k < Hn; k += NTHR)
            Wsh[g * (Hn * JB) + k * JB + jl] = src[k];
    }

    // ---- per-thread constants (update role: warp = local batch, lane = j) ----
    const int bl = wrp;
    const int j = lane;
    const int jg = js * JB + j;
    const int bg = bs * BB + bl;
    const float w_ir = W_ih[jg];
    const float w_iz = W_ih[Hn + jg];
    const float w_in = W_ih[2 * Hn + jg];
    const float cbr = b_ih[jg] + b_hh[jg];
    const float cbz = b_ih[Hn + jg] + b_hh[Hn + jg];
    const float bin = b_ih[2 * Hn + jg];
    const float bhn = b_hh[2 * Hn + jg];
    const float Av = A[0];
    float st = state[(size_t)bg * Hn + jg];
    float hold = st;                      // residual starts at state
    const float* xp = x + (size_t)bg * Ln;

    const int kc = wrp;                   // k-loop role: warp = k-chunk

#pragma unroll 1
    for (int t = 0; t < Ln; t++) {
        // ---- stage residual for this block's 8 batches: hs[k*8+b] ----
        if (t == 0) {
            for (int idx = tid; idx < Hn * BB; idx += NTHR) {
                int k = idx & (Hn - 1);
                int b = idx >> 9;
                hs[k * BB + b] = state[(size_t)(bs * BB + b) * Hn + k];
            }
        } else {
            const float4* src = (const float4*)(g_res[(t - 1) & 1]);
            float4* dst = (float4*)hs;
            for (int q = tid; q < (Hn * BB) / 4; q += NTHR) {
                int idx = q * 4;
                int k = idx >> 3;
                int b0 = idx & 7;               // 0 or 4
                dst[q] = src[(k * Bn + bs * BB + b0) >> 2];
            }
        }
        __syncthreads();

        // ---- matvec partials: warp kc covers k in [kc*64, kc*64+64) ----
        unsigned long long acc[12];
#pragma unroll
        for (int i = 0; i < 12; i++) acc[i] = 0ULL;
        {
            const float* wr0 = Wsh + 0 * (Hn * JB) + kc * 64 * JB + j;
            const float* wz0 = Wsh + 1 * (Hn * JB) + kc * 64 * JB + j;
            const float* wn0 = Wsh + 2 * (Hn * JB) + kc * 64 * JB + j;
            const ulonglong2* hp = (const ulonglong2*)(hs + kc * 64 * BB);
#pragma unroll 8
            for (int kk = 0; kk < 64; kk++) {
                unsigned long long wr2 = pack2(wr0[kk * JB]);
                unsigned long long wz2 = pack2(wz0[kk * JB]);
                unsigned long long wn2 = pack2(wn0[kk * JB]);
                ulonglong2 hA = hp[kk * 2];        // batches 0,1 | 2,3 (broadcast)
                ulonglong2 hB = hp[kk * 2 + 1];    // batches 4,5 | 6,7
                fma2(acc[0], wr2, hA.x); fma2(acc[1], wr2, hA.y);
                fma2(acc[2], wr2, hB.x); fma2(acc[3], wr2, hB.y);
                fma2(acc[4], wz2, hA.x); fma2(acc[5], wz2, hA.y);
                fma2(acc[6], wz2, hB.x); fma2(acc[7], wz2, hB.y);
                fma2(acc[8], wn2, hA.x); fma2(acc[9], wn2, hA.y);
                fma2(acc[10], wn2, hB.x); fma2(acc[11], wn2, hB.y);
            }
        }
        __syncthreads();   // everyone done reading hs (scratch overlaps it)

        // ---- write partials: scratch[kc][g*256 + b*32 + j] ----
#pragma unroll
        for (int g = 0; g < 3; g++)
#pragma unroll
            for (int p = 0; p < 4; p++) {
                unsigned long long v = acc[g * 4 + p];
                float lo = __uint_as_float((unsigned)(v & 0xffffffffu));
                float hi = __uint_as_float((unsigned)(v >> 32));
                scratch[kc * 768 + g * 256 + (2 * p) * 32 + j] = lo;
                scratch[kc * 768 + g * 256 + (2 * p + 1) * 32 + j] = hi;
            }
        __syncthreads();

        // ---- reduce over 8 k-chunks + gate math (role: b=wrp, j=lane) ----
        float sr = 0.f, sz = 0.f, sn = 0.f;
#pragma unroll
        for (int c = 0; c < 8; c++) {
            sr += scratch[c * 768 + 0 + bl * 32 + j];
            sz += scratch[c * 768 + 256 + bl * 32 + j];
            sn += scratch[c * 768 + 512 + bl * 32 + j];
        }
        float xv = xp[t];
        float rr = 1.f / (1.f + __expf(-(sr + xv * w_ir + cbr)));
        float zz = 1.f / (1.f + __expf(-(sz + xv * w_iz + cbz)));
        float nn = tanhf(xv * w_in + bin + rr * (sn + bhn));
        hold = (1.f - zz) * nn + zz * hold;     // new residual
        st = fmaf(Av, hold, st);                // accumulator
        out[((size_t)bg * Ln + t) * Hn + jg] = st;
        g_res[t & 1][jg * Bn + bg] = hold;

        // ---- software grid barrier (monotonic counter, all 128 resident) ----
        __syncthreads();
        if (tid == 0) {
            __threadfence();
            atomicAdd(&g_count, 1u);
            unsigned bound = (unsigned)NBLK * (unsigned)(t + 1);
            volatile unsigned* vc = &g_count;
            while (*vc < bound) { }
            __threadfence();
        }
        __syncthreads();
    }

    if (write_final)
        out[(size_t)Bn * Ln * Hn + (size_t)bg * Hn + jg] = st;
}

extern "C" void kernel_launch(void* const* d_in, const int* in_sizes, int n_in,
                              void* d_out, int out_size) {
    const float* x     = (const float*)d_in[0];
    const float* state = (const float*)d_in[1];
    const float* W_ih  = (const float*)d_in[2];
    const float* W_hh  = (const float*)d_in[3];
    const float* b_ih  = (const float*)d_in[4];
    const float* b_hh  = (const float*)d_in[5];
    const float* A     = (const float*)d_in[6];
    float* out = (float*)d_out;

    long long need = (long long)Bn * Ln * Hn + (long long)Bn * Hn;
    int write_final = ((long long)out_size >= need) ? 1 : 0;

    cudaFuncSetAttribute(gru_persistent_kernel,
                         cudaFuncAttributeMaxDynamicSharedMemorySize,
                         (int)SMEM_BYTES);

    init_kernel<<<1, 1>>>();
    gru_persistent_kernel<<<NBLK, NTHR, SMEM_BYTES>>>(
        x, state, W_ih, W_hh, b_ih, b_hh, A, out, write_final);
}

// round 10
// speedup vs baseline: 1.0318x; 1.0318x over previous
#include <cuda_runtime.h>

// ---------------- problem constants ----------------
constexpr int Bn = 64;      // batch
constexpr int Ln = 2048;    // sequence length
constexpr int Hn = 512;     // hidden
constexpr int JS = 16;      // j-slices (hidden split)
constexpr int BSL = 8;      // batch-slices
constexpr int NBLK = JS * BSL;   // 128 blocks, one per SM
constexpr int JB = Hn / JS;      // 32 hidden cols per block
constexpr int BB = Bn / BSL;     // 8 batches per block
constexpr int NTHR = 512;        // 16 warps -> 4 per SMSP (was 8 -> 2/SMSP)
constexpr int NW = 16;
constexpr int KC = Hn / NW;      // 32 k per warp

// Shared layout (floats):
//   Wsh[3][512][32]  : 49152  (gate-major, k-major, j contiguous -> conflict-free LDS)
//   union { hs[512][8] : 4096 ; scratch[8][768] : 6144 }
constexpr int WSH_FLOATS = 3 * Hn * JB;          // 49152
constexpr int UNION_FLOATS = 8 * 768;            // 6144
constexpr int SMEM_FLOATS = WSH_FLOATS + UNION_FLOATS;  // 55296
constexpr size_t SMEM_BYTES = (size_t)SMEM_FLOATS * 4;  // 221184 B <= 227KB

// Cross-step residual exchange, transposed layout [k*64 + b]:
// consumer staging reads are coalesced float4, producer writes scattered.
__device__ float g_res[2][Hn * Bn];
__device__ unsigned g_count;

__global__ void init_kernel() { g_count = 0u; }

__device__ __forceinline__ unsigned long long pack2(float v) {
    unsigned long long r;
    unsigned u = __float_as_uint(v);
    asm("mov.b64 %0, {%1, %1};" : "=l"(r) : "r"(u));
    return r;
}
__device__ __forceinline__ void fma2(unsigned long long& d,
                                     unsigned long long a,
                                     unsigned long long b) {
    asm("fma.rn.f32x2 %0, %1, %2, %0;" : "+l"(d) : "l"(a), "l"(b));
}
__device__ __forceinline__ float lo32(unsigned long long v) {
    return __uint_as_float((unsigned)(v & 0xffffffffu));
}
__device__ __forceinline__ float hi32(unsigned long long v) {
    return __uint_as_float((unsigned)(v >> 32));
}

extern "C" __global__ void __launch_bounds__(NTHR, 1)
gru_persistent_kernel(const float* __restrict__ x,
                      const float* __restrict__ state,
                      const float* __restrict__ W_ih,
                      const float* __restrict__ W_hh,
                      const float* __restrict__ b_ih,
                      const float* __restrict__ b_hh,
                      const float* __restrict__ A,
                      float* __restrict__ out,
                      int write_final)
{
    extern __shared__ float smem[];
    float* Wsh = smem;                       // 49152 floats
    float* hs = smem + WSH_FLOATS;           // union region (4096 used)
    float* scratch = smem + WSH_FLOATS;      // union region (6144 used)

    const int tid = threadIdx.x;
    const int js = blockIdx.x % JS;
    const int bs = blockIdx.x / JS;
    const int lane = tid & 31;
    const int wrp = tid >> 5;

    // ---- one-time: weights slice into SMEM, layout Wsh[g][k][j] ----
    for (int r = 0; r < 3 * JB; r++) {
        int g = r >> 5, jl = r & 31;
        const float* src = W_hh + (size_t)(g * Hn + js * JB + jl) * Hn;
        for (int k = tid; k < Hn; k += NTHR)
            Wsh[g * (Hn * JB) + k * JB + jl] = src[k];
    }

    // ---- per-thread constants (gate role lives in warps 0..7: b=wrp, j=lane) ----
    const int bl = wrp;                  // gate-phase batch (valid for wrp < 8)
    const int j = lane;
    const int jg = js * JB + j;
    const int bg = bs * BB + (bl & 7);
    const float w_ir = W_ih[jg];
    const float w_iz = W_ih[Hn + jg];
    const float w_in = W_ih[2 * Hn + jg];
    const float cbr = b_ih[jg] + b_hh[jg];
    const float cbz = b_ih[Hn + jg] + b_hh[Hn + jg];
    const float bin = b_ih[2 * Hn + jg];
    const float bhn = b_hh[2 * Hn + jg];
    const float Av = A[0];
    float st = state[(size_t)bg * Hn + jg];
    float hold = st;                      // residual starts at state
    const float* xp = x + (size_t)bg * Ln;

    const int kc = wrp;                   // matvec role: warp = k-chunk of 32

#pragma unroll 1
    for (int t = 0; t < Ln; t++) {
        // ---- stage residual for this block's 8 batches: hs[k*8+b] ----
        if (t == 0) {
            for (int idx = tid; idx < Hn * BB; idx += NTHR) {
                int k = idx & (Hn - 1);
                int b = idx >> 9;
                hs[k * BB + b] = state[(size_t)(bs * BB + b) * Hn + k];
            }
        } else {
            const float4* src = (const float4*)(g_res[(t - 1) & 1]);
            float4* dst = (float4*)hs;
#pragma unroll
            for (int q = tid; q < (Hn * BB) / 4; q += NTHR) {
                int idx = q * 4;
                int k = idx >> 3;
                int b0 = idx & 7;               // 0 or 4
                dst[q] = __ldcg(&src[(k * Bn + bs * BB + b0) >> 2]); // L1-bypass
            }
        }
        __syncthreads();

        // ---- matvec partials: warp kc covers k in [kc*32, kc*32+32) ----
        unsigned long long acc[12];
#pragma unroll
        for (int i = 0; i < 12; i++) acc[i] = 0ULL;
        {
            const float* wr0 = Wsh + 0 * (Hn * JB) + kc * KC * JB + j;
            const float* wz0 = Wsh + 1 * (Hn * JB) + kc * KC * JB + j;
            const float* wn0 = Wsh + 2 * (Hn * JB) + kc * KC * JB + j;
            const ulonglong2* hp = (const ulonglong2*)(hs + kc * KC * BB);
#pragma unroll 8
            for (int kk = 0; kk < KC; kk++) {
                unsigned long long wr2 = pack2(wr0[kk * JB]);
                unsigned long long wz2 = pack2(wz0[kk * JB]);
                unsigned long long wn2 = pack2(wn0[kk * JB]);
                ulonglong2 hA = hp[kk * 2];        // batches 0,1 | 2,3 (broadcast)
                ulonglong2 hB = hp[kk * 2 + 1];    // batches 4,5 | 6,7
                fma2(acc[0], wr2, hA.x); fma2(acc[1], wr2, hA.y);
                fma2(acc[2], wr2, hB.x); fma2(acc[3], wr2, hB.y);
                fma2(acc[4], wz2, hA.x); fma2(acc[5], wz2, hA.y);
                fma2(acc[6], wz2, hB.x); fma2(acc[7], wz2, hB.y);
                fma2(acc[8], wn2, hA.x); fma2(acc[9], wn2, hA.y);
                fma2(acc[10], wn2, hB.x); fma2(acc[11], wn2, hB.y);
            }
        }
        __syncthreads();   // everyone done reading hs (scratch overlaps it)

        // ---- hierarchical reduce round 1: warps 8..15 spill to slot wrp-8 ----
        if (wrp >= 8) {
            float* sl = scratch + (wrp - 8) * 768;
#pragma unroll
            for (int g = 0; g < 3; g++)
#pragma unroll
                for (int p = 0; p < 4; p++) {
                    unsigned long long v = acc[g * 4 + p];
                    sl[g * 256 + (2 * p) * 32 + j] = lo32(v);
                    sl[g * 256 + (2 * p + 1) * 32 + j] = hi32(v);
                }
        }
        __syncthreads();

        // ---- round 2: warps 0..7 merge slot wrp into registers, write back ----
        if (wrp < 8) {
            float* sl = scratch + wrp * 768;
#pragma unroll
            for (int g = 0; g < 3; g++)
#pragma unroll
                for (int p = 0; p < 4; p++) {
                    unsigned long long v = acc[g * 4 + p];
                    float lo = lo32(v) + sl[g * 256 + (2 * p) * 32 + j];
                    float hi = hi32(v) + sl[g * 256 + (2 * p + 1) * 32 + j];
                    sl[g * 256 + (2 * p) * 32 + j] = lo;
                    sl[g * 256 + (2 * p + 1) * 32 + j] = hi;
                }
        }
        __syncthreads();

        // ---- gate phase (warps 0..7: b=wrp, j=lane) ----
        if (wrp < 8) {
            float xv = __ldcg(&xp[t]);       // issue early; hides under reduce
            float sr = 0.f, sz = 0.f, sn = 0.f;
#pragma unroll
            for (int c = 0; c < 8; c++) {
                sr += scratch[c * 768 + 0 + bl * 32 + j];
                sz += scratch[c * 768 + 256 + bl * 32 + j];
                sn += scratch[c * 768 + 512 + bl * 32 + j];
            }
            float rr = 1.f / (1.f + __expf(-(sr + xv * w_ir + cbr)));
            float zz = 1.f / (1.f + __expf(-(sz + xv * w_iz + cbz)));
            float nn = tanhf(xv * w_in + bin + rr * (sn + bhn));
            hold = (1.f - zz) * nn + zz * hold;     // new residual
            st = fmaf(Av, hold, st);                // accumulator
            g_res[t & 1][jg * Bn + bg] = hold;      // critical cross-step write
            out[((size_t)bg * Ln + t) * Hn + jg] = st;  // fire-and-forget
        }

        // ---- software grid barrier (monotonic counter, all 128 resident) ----
        __syncthreads();
        if (tid == 0) {
            __threadfence();
            atomicAdd(&g_count, 1u);
            unsigned bound = (unsigned)NBLK * (unsigned)(t + 1);
            volatile unsigned* vc = &g_count;
            while (*vc < bound) { }
            __threadfence();
        }
        __syncthreads();
    }

    if (write_final && wrp < 8)
        out[(size_t)Bn * Ln * Hn + (size_t)bg * Hn + jg] = st;
}

extern "C" void kernel_launch(void* const* d_in, const int* in_sizes, int n_in,
                              void* d_out, int out_size) {
    const float* x     = (const float*)d_in[0];
    const float* state = (const float*)d_in[1];
    const float* W_ih  = (const float*)d_in[2];
    const float* W_hh  = (const float*)d_in[3];
    const float* b_ih  = (const float*)d_in[4];
    const float* b_hh  = (const float*)d_in[5];
    const float* A     = (const float*)d_in[6];
    float* out = (float*)d_out;

    long long need = (long long)Bn * Ln * Hn + (long long)Bn * Hn;
    int write_final = ((long long)out_size >= need) ? 1 : 0;

    cudaFuncSetAttribute(gru_persistent_kernel,
                         cudaFuncAttributeMaxDynamicSharedMemorySize,
                         (int)SMEM_BYTES);

    init_kernel<<<1, 1>>>();
    gru_persistent_kernel<<<NBLK, NTHR, SMEM_BYTES>>>(
        x, state, W_ih, W_hh, b_ih, b_hh, A, out, write_final);
}

// round 12
// speedup vs baseline: 1.1273x; 1.0925x over previous
#include <cuda_runtime.h>

// ---------------- problem constants ----------------
constexpr int Bn = 64;      // batch
constexpr int Ln = 2048;    // sequence length
constexpr int Hn = 512;     // hidden
constexpr int JS = 16;      // j-slices (hidden split)
constexpr int BSL = 8;      // batch-slices
constexpr int NBLK = JS * BSL;   // 128 blocks, one per SM
constexpr int JB = Hn / JS;      // 32 hidden cols per block
constexpr int BB = Bn / BSL;     // 8 batches per block
constexpr int NTHR = 512;        // 16 warps
constexpr int NW = 16;
constexpr int KC = Hn / NW;      // 32 k per warp

// Shared layout (floats):
//   Wsh[3][512][32]  : 49152  (gate-major, k-major, j contiguous, conflict-free)
//   union { hs[512][8] : 4096 ; scratch[8][768] : 6144 }
constexpr int WSH_FLOATS = 3 * Hn * JB;          // 49152
constexpr int UNION_FLOATS = 8 * 768;            // 6144
constexpr int SMEM_FLOATS = WSH_FLOATS + UNION_FLOATS;  // 55296
constexpr size_t SMEM_BYTES = (size_t)SMEM_FLOATS * 4;  // 221184 B <= 227KB

// Cross-step residual exchange, transposed layout [k*64 + b].
__device__ float g_res[2][Hn * Bn];
// Per-producer epoch flags: group bs, producer js. 128B stride (own line).
__device__ unsigned g_flag[BSL * JS * 32];

__global__ void init_kernel() {
    int i = threadIdx.x;
    if (i < BSL * JS) g_flag[i * 32] = 0u;
}

__device__ __forceinline__ unsigned long long pack2(float v) {
    unsigned long long r;
    unsigned u = __float_as_uint(v);
    asm("mov.b64 %0, {%1, %1};" : "=l"(r) : "r"(u));
    return r;
}
__device__ __forceinline__ void fma2(unsigned long long& d,
                                     unsigned long long a,
                                     unsigned long long b) {
    asm("fma.rn.f32x2 %0, %1, %2, %0;" : "+l"(d) : "l"(a), "l"(b));
}
__device__ __forceinline__ float lo32(unsigned long long v) {
    return __uint_as_float((unsigned)(v & 0xffffffffu));
}
__device__ __forceinline__ float hi32(unsigned long long v) {
    return __uint_as_float((unsigned)(v >> 32));
}
__device__ __forceinline__ unsigned ld_acquire_gpu(const unsigned* p) {
    unsigned v;
    asm volatile("ld.acquire.gpu.b32 %0, [%1];" : "=r"(v) : "l"(p) : "memory");
    return v;
}
__device__ __forceinline__ void st_release_gpu(unsigned* p, unsigned v) {
    asm volatile("st.release.gpu.b32 [%0], %1;" :: "l"(p), "r"(v) : "memory");
}

extern "C" __global__ void __launch_bounds__(NTHR, 1)
gru_persistent_kernel(const float* __restrict__ x,
                      const float* __restrict__ state,
                      const float* __restrict__ W_ih,
                      const float* __restrict__ W_hh,
                      const float* __restrict__ b_ih,
                      const float* __restrict__ b_hh,
                      const float* __restrict__ A,
                      float* __restrict__ out,
                      int write_final)
{
    extern __shared__ float smem[];
    float* Wsh = smem;                       // 49152 floats
    float* hs = smem + WSH_FLOATS;           // union region (4096 used)
    float* scratch = smem + WSH_FLOATS;      // union region (6144 used)

    const int tid = threadIdx.x;
    const int js = blockIdx.x % JS;
    const int bs = blockIdx.x / JS;
    const int lane = tid & 31;
    const int wrp = tid >> 5;

    // ---- one-time: weights slice into SMEM, layout Wsh[g][k][j] ----
    for (int r = 0; r < 3 * JB; r++) {
        int g = r >> 5, jl = r & 31;
        const float* src = W_hh + (size_t)(g * Hn + js * JB + jl) * Hn;
        for (int k = tid; k < Hn; k += NTHR)
            Wsh[g * (Hn * JB) + k * JB + jl] = src[k];
    }

    // ---- per-thread constants (gate role: warps 0..7, b=wrp, j=lane) ----
    const int bl = wrp;
    const int j = lane;
    const int jg = js * JB + j;
    const int bg = bs * BB + (bl & 7);
    const float w_ir = W_ih[jg];
    const float w_iz = W_ih[Hn + jg];
    const float w_in = W_ih[2 * Hn + jg];
    const float cbr = b_ih[jg] + b_hh[jg];
    const float cbz = b_ih[Hn + jg] + b_hh[Hn + jg];
    const float bin = b_ih[2 * Hn + jg];
    const float bhn = b_hh[2 * Hn + jg];
    const float Av = A[0];
    float st = state[(size_t)bg * Hn + jg];
    float hold = st;                      // residual starts at state
    const float* xp = x + (size_t)bg * Ln;

    const int kc = wrp;                   // matvec role: warp = k-chunk of 32
    // This warp's flag to wait on = producer with js' == wrp, same bs group.
    unsigned* my_flag = g_flag + ((bs * JS + wrp) << 5);
    unsigned* our_flag = g_flag + ((bs * JS + js) << 5);

    __syncthreads();   // Wsh ready

#pragma unroll 1
    for (int t = 0; t < Ln; t++) {
        // ---- per-warp staging: warp w stages producer w's chunk into ITS
        //      OWN hs chunk (only this warp reads it). No block sync needed.
        if (t == 0) {
            for (int i = lane; i < KC * BB; i += 32) {
                int k_off = i >> 3, b = i & 7;
                hs[(wrp * KC + k_off) * BB + b] =
                    state[(size_t)(bs * BB + b) * Hn + wrp * KC + k_off];
            }
        } else {
            const unsigned want = (unsigned)t;
            while (ld_acquire_gpu(my_flag) < want) { }
            const float4* src = (const float4*)(g_res[(t - 1) & 1]);
            float4* dst = (float4*)hs;
#pragma unroll
            for (int it = 0; it < 2; it++) {
                int l = lane + it * 32;           // 0..63
                int k = wrp * KC + (l >> 1);
                int bq = l & 1;                    // float4 index of b0 (0 or 1)
                dst[k * 2 + bq] = __ldcg(&src[k * 16 + bs * 2 + bq]);
            }
        }
        __syncwarp();

        // ---- matvec partials: warp kc covers k in [kc*32, kc*32+32) ----
        unsigned long long acc[12];
#pragma unroll
        for (int i = 0; i < 12; i++) acc[i] = 0ULL;
        {
            const float* wr0 = Wsh + 0 * (Hn * JB) + kc * KC * JB + j;
            const float* wz0 = Wsh + 1 * (Hn * JB) + kc * KC * JB + j;
            const float* wn0 = Wsh + 2 * (Hn * JB) + kc * KC * JB + j;
            const ulonglong2* hp = (const ulonglong2*)(hs + kc * KC * BB);
#pragma unroll 8
            for (int kk = 0; kk < KC; kk++) {
                unsigned long long wr2 = pack2(wr0[kk * JB]);
                unsigned long long wz2 = pack2(wz0[kk * JB]);
                unsigned long long wn2 = pack2(wn0[kk * JB]);
                ulonglong2 hA = hp[kk * 2];        // batches 0,1 | 2,3 (bcast)
                ulonglong2 hB = hp[kk * 2 + 1];    // batches 4,5 | 6,7
                fma2(acc[0], wr2, hA.x); fma2(acc[1], wr2, hA.y);
                fma2(acc[2], wr2, hB.x); fma2(acc[3], wr2, hB.y);
                fma2(acc[4], wz2, hA.x); fma2(acc[5], wz2, hA.y);
                fma2(acc[6], wz2, hB.x); fma2(acc[7], wz2, hB.y);
                fma2(acc[8], wn2, hA.x); fma2(acc[9], wn2, hA.y);
                fma2(acc[10], wn2, hB.x); fma2(acc[11], wn2, hB.y);
            }
        }
        __syncthreads();   // S1: all hs reads done (scratch overlaps hs)

        // ---- reduce round 1: warps 8..15 spill to slot wrp-8 ----
        if (wrp >= 8) {
            float* sl = scratch + (wrp - 8) * 768;
#pragma unroll
            for (int g = 0; g < 3; g++)
#pragma unroll
                for (int p = 0; p < 4; p++) {
                    unsigned long long v = acc[g * 4 + p];
                    sl[g * 256 + (2 * p) * 32 + j] = lo32(v);
                    sl[g * 256 + (2 * p + 1) * 32 + j] = hi32(v);
                }
        }
        __syncthreads();   // S2

        // ---- round 2: warps 0..7 merge slot wrp, write back ----
        if (wrp < 8) {
            float* sl = scratch + wrp * 768;
#pragma unroll
            for (int g = 0; g < 3; g++)
#pragma unroll
                for (int p = 0; p < 4; p++) {
                    unsigned long long v = acc[g * 4 + p];
                    float lo = lo32(v) + sl[g * 256 + (2 * p) * 32 + j];
                    float hi = hi32(v) + sl[g * 256 + (2 * p + 1) * 32 + j];
                    sl[g * 256 + (2 * p) * 32 + j] = lo;
                    sl[g * 256 + (2 * p + 1) * 32 + j] = hi;
                }
        }
        __syncthreads();   // S3

        // ---- gate phase (warps 0..7: b=wrp, j=lane) ----
        if (wrp < 8) {
            float xv = __ldcg(&xp[t]);
            float sr = 0.f, sz = 0.f, sn = 0.f;
#pragma unroll
            for (int c = 0; c < 8; c++) {
                sr += scratch[c * 768 + 0 + bl * 32 + j];
                sz += scratch[c * 768 + 256 + bl * 32 + j];
                sn += scratch[c * 768 + 512 + bl * 32 + j];
            }
            float rr = 1.f / (1.f + __expf(-(sr + xv * w_ir + cbr)));
            float zz = 1.f / (1.f + __expf(-(sz + xv * w_iz + cbz)));
            float nn = tanhf(xv * w_in + bin + rr * (sn + bhn));
            hold = (1.f - zz) * nn + zz * hold;     // new residual
            st = fmaf(Av, hold, st);                // accumulator
            g_res[t & 1][jg * Bn + bg] = hold;      // cross-step publish
            out[((size_t)bg * Ln + t) * Hn + jg] = st;  // fire-and-forget
        }

        // ---- publish epoch: group-local flag, release semantics ----
        __syncthreads();   // S4: gate scratch reads done; h writes ordered
        if (tid == 0) {
            __threadfence();
            st_release_gpu(our_flag, (unsigned)(t + 1));
        }
        // next iteration's staging writes hs only after S4 in program order
    }

    if (write_final && wrp < 8)
        out[(size_t)Bn * Ln * Hn + (size_t)bg * Hn + jg] = st;
}

extern "C" void kernel_launch(void* const* d_in, const int* in_sizes, int n_in,
                              void* d_out, int out_size) {
    const float* x     = (const float*)d_in[0];
    const float* state = (const float*)d_in[1];
    const float* W_ih  = (const float*)d_in[2];
    const float* W_hh  = (const float*)d_in[3];
    const float* b_ih  = (const float*)d_in[4];
    const float* b_hh  = (const float*)d_in[5];
    const float* A     = (const float*)d_in[6];
    float* out = (float*)d_out;

    long long need = (long long)Bn * Ln * Hn + (long long)Bn * Hn;
    int write_final = ((long long)out_size >= need) ? 1 : 0;

    cudaFuncSetAttribute(gru_persistent_kernel,
                         cudaFuncAttributeMaxDynamicSharedMemorySize,
                         (int)SMEM_BYTES);

    init_kernel<<<1, 128>>>();
    gru_persistent_kernel<<<NBLK, NTHR, SMEM_BYTES>>>(
        x, state, W_ih, W_hh, b_ih, b_hh, A, out, write_final);
}